// round 4
// baseline (speedup 1.0000x reference)
#include <cuda_runtime.h>

#define NN 50000
#define NE 800000
#define HID 64
#define NG 64

// ---------------- persistent device scratch (allocation-free) ----------------
// zeroed-per-call region (single memsetAsync)
struct ZBlock {
    int   deg[NN];
    int   cnt[NG];
    int   ticket;
    int   pad[3];
    float pool[NG * HID];
};
__device__ ZBlock g_z;

__device__ __align__(16) float g_bufA[NN * HID];   // layer inputs (post-LN)
__device__ __align__(16) float g_bufB[NN * HID];   // hs = (x@W) * dinv
__device__ __align__(16) float g_e4s[NN * 4];      // emb[node]*dinv
__device__ float g_dinv[NN];
__device__ int   g_rowbeg[NN];
__device__ int   g_rank[NE];
__device__ int   g_col[NE];

// ---------------- setup kernels ----------------
__global__ __launch_bounds__(256) void k_deg(const int* __restrict__ dst) {
    int e = blockIdx.x * blockDim.x + threadIdx.x;
    if (e < NE) g_rank[e] = atomicAdd(&g_z.deg[dst[e]], 1);
}

// single-pass scan: per-block inclusive scan + global ticket for block base.
// also computes dinv and e4s = emb[node]*dinv.
__global__ __launch_bounds__(256) void k_scan(const int* __restrict__ node,
                                              const float* __restrict__ emb) {
    __shared__ int sh[256];
    __shared__ int base;
    int t = threadIdx.x;
    int i = blockIdx.x * 256 + t;
    int d = (i < NN) ? g_z.deg[i] : 0;
    sh[t] = d;
    __syncthreads();
    for (int o = 1; o < 256; o <<= 1) {
        int v = (t >= o) ? sh[t - o] : 0;
        __syncthreads();
        sh[t] += v;
        __syncthreads();
    }
    if (t == 255) base = atomicAdd(&g_z.ticket, sh[255]);
    __syncthreads();
    if (i < NN) {
        g_rowbeg[i] = base + sh[t] - d;
        float di = rsqrtf((float)(d + 1));
        g_dinv[i] = di;
        float4 e = ((const float4*)emb)[node[i]];
        ((float4*)g_e4s)[i] = make_float4(e.x * di, e.y * di, e.z * di, e.w * di);
    }
}

// pure scatter: no atomics (rank captured in k_deg)
__global__ __launch_bounds__(256) void k_fill(const int* __restrict__ src,
                                              const int* __restrict__ dst) {
    int e = blockIdx.x * blockDim.x + threadIdx.x;
    if (e < NE) {
        int d = dst[e];
        g_col[g_rowbeg[d] + g_rank[e]] = src[e];
    }
}

// ---------------- layer 1 fully fused: 4-dim gather + (4->64 proj) + bias + relu + LN ----------------
__global__ __launch_bounds__(128) void k_layer1(const float* __restrict__ W1,
                                                const float* __restrict__ b1,
                                                const float* __restrict__ lng,
                                                const float* __restrict__ lnb) {
    __shared__ float sW[4 * HID];
    int t = threadIdx.x;
    sW[t] = W1[t];
    sW[t + 128] = W1[t + 128];
    __syncthreads();
    int n = blockIdx.x * 128 + t;
    if (n >= NN) return;
    const float4* e4 = (const float4*)g_e4s;
    float4 agg = __ldg(&e4[n]);  // self term (gets extra dinv below)
    int beg = g_rowbeg[n];
    int end = beg + g_z.deg[n];
    int e = beg;
    for (; e + 4 <= end; e += 4) {
        float4 v0 = __ldg(&e4[__ldg(&g_col[e])]);
        float4 v1 = __ldg(&e4[__ldg(&g_col[e + 1])]);
        float4 v2 = __ldg(&e4[__ldg(&g_col[e + 2])]);
        float4 v3 = __ldg(&e4[__ldg(&g_col[e + 3])]);
        agg.x += (v0.x + v1.x) + (v2.x + v3.x);
        agg.y += (v0.y + v1.y) + (v2.y + v3.y);
        agg.z += (v0.z + v1.z) + (v2.z + v3.z);
        agg.w += (v0.w + v1.w) + (v2.w + v3.w);
    }
    for (; e < end; e++) {
        float4 v = __ldg(&e4[__ldg(&g_col[e])]);
        agg.x += v.x; agg.y += v.y; agg.z += v.z; agg.w += v.w;
    }
    float di = g_dinv[n];
    // out = dinv[n]*(Sum_src e4s[src] + e4s[n])
    agg.x *= di; agg.y *= di; agg.z *= di; agg.w *= di;
    float v[HID];
    float mu = 0.f;
#pragma unroll
    for (int j = 0; j < HID; j++) {
        float r = fmaf(agg.x, sW[j], fmaf(agg.y, sW[64 + j],
                  fmaf(agg.z, sW[128 + j], fmaf(agg.w, sW[192 + j], __ldg(&b1[j])))));
        r = fmaxf(r, 0.f);
        v[j] = r;
        mu += r;
    }
    mu *= (1.f / 64.f);
    float var = 0.f;
#pragma unroll
    for (int j = 0; j < HID; j++) {
        float d = v[j] - mu;
        v[j] = d;
        var = fmaf(d, d, var);
    }
    float rs = rsqrtf(var * (1.f / 64.f) + 1e-5f);
    float4* o = (float4*)(g_bufA + (size_t)n * HID);
#pragma unroll
    for (int j4 = 0; j4 < 16; j4++) {
        float r[4];
#pragma unroll
        for (int u = 0; u < 4; u++) {
            int j = 4 * j4 + u;
            r[u] = fmaf(v[j] * rs, __ldg(&lng[j]), __ldg(&lnb[j]));
        }
        o[j4] = make_float4(r[0], r[1], r[2], r[3]);
    }
}

// ---------------- layers 2/3 dense: hs = (bufA @ W) * dinv ----------------
__global__ __launch_bounds__(128) void k_mm(const float* __restrict__ W) {
    __shared__ float sW[HID * HID];
    int t = threadIdx.x;
    for (int i = t; i < HID * HID; i += 128) sW[i] = W[i];
    __syncthreads();
    int n = blockIdx.x * 128 + t;
    if (n >= NN) return;
    float acc[HID];
#pragma unroll
    for (int j = 0; j < HID; j++) acc[j] = 0.f;
    const float4* x4 = (const float4*)(g_bufA + (size_t)n * HID);
    for (int k4 = 0; k4 < 16; k4++) {
        float4 xv = x4[k4];
        const float4* w0 = (const float4*)(sW + (4 * k4 + 0) * HID);
        const float4* w1 = (const float4*)(sW + (4 * k4 + 1) * HID);
        const float4* w2 = (const float4*)(sW + (4 * k4 + 2) * HID);
        const float4* w3 = (const float4*)(sW + (4 * k4 + 3) * HID);
#pragma unroll
        for (int j = 0; j < 16; j++) {
            float4 a = w0[j], b = w1[j], c = w2[j], d = w3[j];
            acc[4 * j + 0] = fmaf(xv.x, a.x, fmaf(xv.y, b.x, fmaf(xv.z, c.x, fmaf(xv.w, d.x, acc[4 * j + 0]))));
            acc[4 * j + 1] = fmaf(xv.x, a.y, fmaf(xv.y, b.y, fmaf(xv.z, c.y, fmaf(xv.w, d.y, acc[4 * j + 1]))));
            acc[4 * j + 2] = fmaf(xv.x, a.z, fmaf(xv.y, b.z, fmaf(xv.z, c.z, fmaf(xv.w, d.z, acc[4 * j + 2]))));
            acc[4 * j + 3] = fmaf(xv.x, a.w, fmaf(xv.y, b.w, fmaf(xv.z, c.w, fmaf(xv.w, d.w, acc[4 * j + 3]))));
        }
    }
    float di = g_dinv[n];
    float4* o = (float4*)(g_bufB + (size_t)n * HID);
#pragma unroll
    for (int j = 0; j < 16; j++)
        o[j] = make_float4(acc[4 * j] * di, acc[4 * j + 1] * di, acc[4 * j + 2] * di, acc[4 * j + 3] * di);
}

// ---------------- fused 64-dim gather + relu (+LN | +pool), warp per node ----------------
template <bool LN, bool POOL>
__global__ __launch_bounds__(256) void k_gather(const float* __restrict__ bias,
                                                const float* __restrict__ lng,
                                                const float* __restrict__ lnb,
                                                const int* __restrict__ batch) {
    int n = (blockIdx.x * blockDim.x + threadIdx.x) >> 5;
    int lane = threadIdx.x & 31;
    if (n >= NN) return;
    const float2* hs2 = (const float2*)g_bufB;
    float2 acc = __ldg(&hs2[(size_t)n * 32 + lane]);  // self-loop term (pre-scaled)
    int beg = g_rowbeg[n];
    int end = beg + g_z.deg[n];
    int e = beg;
    int m8 = beg + ((end - beg) & ~7);
    for (; e < m8; e += 8) {
        int s0 = __ldg(&g_col[e + 0]), s1 = __ldg(&g_col[e + 1]);
        int s2 = __ldg(&g_col[e + 2]), s3 = __ldg(&g_col[e + 3]);
        int s4 = __ldg(&g_col[e + 4]), s5 = __ldg(&g_col[e + 5]);
        int s6 = __ldg(&g_col[e + 6]), s7 = __ldg(&g_col[e + 7]);
        float2 v0 = __ldg(&hs2[(size_t)s0 * 32 + lane]);
        float2 v1 = __ldg(&hs2[(size_t)s1 * 32 + lane]);
        float2 v2 = __ldg(&hs2[(size_t)s2 * 32 + lane]);
        float2 v3 = __ldg(&hs2[(size_t)s3 * 32 + lane]);
        float2 v4 = __ldg(&hs2[(size_t)s4 * 32 + lane]);
        float2 v5 = __ldg(&hs2[(size_t)s5 * 32 + lane]);
        float2 v6 = __ldg(&hs2[(size_t)s6 * 32 + lane]);
        float2 v7 = __ldg(&hs2[(size_t)s7 * 32 + lane]);
        acc.x += ((v0.x + v1.x) + (v2.x + v3.x)) + ((v4.x + v5.x) + (v6.x + v7.x));
        acc.y += ((v0.y + v1.y) + (v2.y + v3.y)) + ((v4.y + v5.y) + (v6.y + v7.y));
    }
    for (; e < end; e++) {
        int s = __ldg(&g_col[e]);
        float2 v = __ldg(&hs2[(size_t)s * 32 + lane]);
        acc.x += v.x;
        acc.y += v.y;
    }
    float di = g_dinv[n];
    int f = lane * 2;
    float vx = fmaxf(fmaf(di, acc.x, __ldg(&bias[f])), 0.f);
    float vy = fmaxf(fmaf(di, acc.y, __ldg(&bias[f + 1])), 0.f);
    if (LN) {
        float s = vx + vy;
#pragma unroll
        for (int o = 16; o; o >>= 1) s += __shfl_xor_sync(0xffffffffu, s, o);
        float mu = s * (1.f / 64.f);
        float dx = vx - mu, dy = vy - mu;
        float q = dx * dx + dy * dy;
#pragma unroll
        for (int o = 16; o; o >>= 1) q += __shfl_xor_sync(0xffffffffu, q, o);
        float r = rsqrtf(q * (1.f / 64.f) + 1e-5f);
        vx = fmaf(dx * r, __ldg(&lng[f]), __ldg(&lnb[f]));
        vy = fmaf(dy * r, __ldg(&lng[f + 1]), __ldg(&lnb[f + 1]));
    }
    if (POOL) {
        int g = __ldg(&batch[n]);
        atomicAdd(&g_z.pool[g * HID + f], vx);
        atomicAdd(&g_z.pool[g * HID + f + 1], vy);
        if (lane == 0) atomicAdd(&g_z.cnt[g], 1);
    } else {
        ((float2*)g_bufA)[(size_t)n * 32 + lane] = make_float2(vx, vy);
    }
}

// ---------------- final MLP: out = (pool/cnt) @ pW1 + pb1, then @ pW2 + pb2 ----------------
__global__ __launch_bounds__(1024) void k_mlp(const float* __restrict__ pW1,
                                              const float* __restrict__ pb1,
                                              const float* __restrict__ pW2,
                                              const float* __restrict__ pb2,
                                              float* __restrict__ out) {
    __shared__ float sp[NG * HID];
    __shared__ float sh[NG * HID];
    int t = threadIdx.x;  // 1024
    for (int i = t; i < NG * HID; i += 1024) {
        int g = i >> 6;
        float c = (float)max(g_z.cnt[g], 1);
        sp[i] = g_z.pool[i] / c;
    }
    __syncthreads();
    for (int i = t; i < NG * HID; i += 1024) {
        int g = i >> 6, j = i & 63;
        float a = pb1[j];
        for (int k = 0; k < HID; k++) a = fmaf(sp[g * HID + k], pW1[k * HID + j], a);
        sh[i] = a;
    }
    __syncthreads();
    for (int i = t; i < NG * HID; i += 1024) {
        int g = i >> 6, j = i & 63;
        float a = pb2[j];
        for (int k = 0; k < HID; k++) a = fmaf(sh[g * HID + k], pW2[k * HID + j], a);
        out[i] = a;
    }
}

// ---------------- launcher ----------------
extern "C" void kernel_launch(void* const* d_in, const int* in_sizes, int n_in,
                              void* d_out, int out_size) {
    const int* node = (const int*)d_in[0];
    const int* src = (const int*)d_in[1];
    const int* dst = (const int*)d_in[2];
    const int* batch = (const int*)d_in[3];
    const float* emb = (const float*)d_in[4];
    const float* W1 = (const float*)d_in[5];
    const float* b1 = (const float*)d_in[6];
    const float* W2 = (const float*)d_in[7];
    const float* b2 = (const float*)d_in[8];
    const float* W3 = (const float*)d_in[9];
    const float* b3 = (const float*)d_in[10];
    const float* ln1g = (const float*)d_in[11];
    const float* ln1b = (const float*)d_in[12];
    const float* ln2g = (const float*)d_in[13];
    const float* ln2b = (const float*)d_in[14];
    const float* pW1 = (const float*)d_in[15];
    const float* pb1 = (const float*)d_in[16];
    const float* pW2 = (const float*)d_in[17];
    const float* pb2 = (const float*)d_in[18];
    float* out = (float*)d_out;

    // zero deg/cnt/ticket/pool in one shot
    void* zptr = nullptr;
    cudaGetSymbolAddress(&zptr, g_z);
    cudaMemsetAsync(zptr, 0, sizeof(ZBlock));

    const int TB = 256;
    k_deg<<<(NE + TB - 1) / TB, TB>>>(dst);
    k_scan<<<(NN + TB - 1) / TB, TB>>>(node, emb);
    k_fill<<<(NE + TB - 1) / TB, TB>>>(src, dst);

    dim3 gmm((NN + 127) / 128);
    dim3 ggt((NN * 32 + TB - 1) / TB);

    // layer 1 (fully fused)
    k_layer1<<<gmm, 128>>>(W1, b1, ln1g, ln1b);
    // layer 2
    k_mm<<<gmm, 128>>>(W2);
    k_gather<true, false><<<ggt, TB>>>(b2, ln2g, ln2b, nullptr);
    // layer 3 (+ fused mean-pool accumulate)
    k_mm<<<gmm, 128>>>(W3);
    k_gather<false, true><<<ggt, TB>>>(b3, nullptr, nullptr, batch);
    // MLP head
    k_mlp<<<1, 1024>>>(pW1, pb1, pW2, pb2, out);
}

// round 5
// speedup vs baseline: 1.0110x; 1.0110x over previous
#include <cuda_runtime.h>
#include <cuda_fp16.h>

#define NN 50000
#define NE 800000
#define HID 64
#define NG 64

// ---------------- persistent device scratch (allocation-free) ----------------
// zeroed-per-call region (single memsetAsync)
struct ZBlock {
    int   deg[NN];
    int   cnt[NG];
    int   ticket;
    int   pad[3];
    float pool[NG * HID];
};
__device__ ZBlock g_z;

__device__ __align__(16) float  g_bufA[NN * HID];     // layer inputs (post-LN), fp32
__device__ __align__(16) __half2 g_bufH[NN * HID / 2]; // hs = (x@W)*dinv, fp16 messages
__device__ __align__(16) float  g_e4s[NN * 4];        // emb[node]*dinv
__device__ float g_dinv[NN];
__device__ int   g_rowbeg[NN];
__device__ int   g_rank[NE];
__device__ int   g_col[NE];

// ---------------- setup kernels ----------------
__global__ __launch_bounds__(256) void k_deg(const int* __restrict__ dst) {
    int e = blockIdx.x * blockDim.x + threadIdx.x;
    if (e < NE) g_rank[e] = atomicAdd(&g_z.deg[dst[e]], 1);
}

// single-pass scan: per-block inclusive scan + global ticket for block base.
// also computes dinv and e4s = emb[node]*dinv.
__global__ __launch_bounds__(256) void k_scan(const int* __restrict__ node,
                                              const float* __restrict__ emb) {
    __shared__ int sh[256];
    __shared__ int base;
    int t = threadIdx.x;
    int i = blockIdx.x * 256 + t;
    int d = (i < NN) ? g_z.deg[i] : 0;
    sh[t] = d;
    __syncthreads();
    for (int o = 1; o < 256; o <<= 1) {
        int v = (t >= o) ? sh[t - o] : 0;
        __syncthreads();
        sh[t] += v;
        __syncthreads();
    }
    if (t == 255) base = atomicAdd(&g_z.ticket, sh[255]);
    __syncthreads();
    if (i < NN) {
        g_rowbeg[i] = base + sh[t] - d;
        float di = rsqrtf((float)(d + 1));
        g_dinv[i] = di;
        float4 e = ((const float4*)emb)[node[i]];
        ((float4*)g_e4s)[i] = make_float4(e.x * di, e.y * di, e.z * di, e.w * di);
    }
}

// pure scatter: no atomics (rank captured in k_deg)
__global__ __launch_bounds__(256) void k_fill(const int* __restrict__ src,
                                              const int* __restrict__ dst) {
    int e = blockIdx.x * blockDim.x + threadIdx.x;
    if (e < NE) {
        int d = dst[e];
        g_col[g_rowbeg[d] + g_rank[e]] = src[e];
    }
}

// ---------------- layer 1 fused, WARP per node ----------------
// lanes gather edges in parallel (4-dim), butterfly all-reduce,
// each lane computes 2 of 64 outputs, warp LayerNorm, write bufA.
__global__ __launch_bounds__(256) void k_layer1(const float* __restrict__ W1,
                                                const float* __restrict__ b1,
                                                const float* __restrict__ lng,
                                                const float* __restrict__ lnb) {
    __shared__ float sW[4 * HID];   // [k][j]
    int t = threadIdx.x;
    sW[t] = W1[t];  // 256 threads == 256 elements
    __syncthreads();
    int n = (blockIdx.x * 256 + t) >> 5;
    int lane = t & 31;
    if (n >= NN) return;
    const float4* e4 = (const float4*)g_e4s;
    int beg = g_rowbeg[n];
    int end = beg + g_z.deg[n];
    float ax = 0.f, ay = 0.f, az = 0.f, aw = 0.f;
    for (int e = beg + lane; e < end; e += 32) {
        float4 v = __ldg(&e4[__ldg(&g_col[e])]);
        ax += v.x; ay += v.y; az += v.z; aw += v.w;
    }
#pragma unroll
    for (int o = 16; o; o >>= 1) {
        ax += __shfl_xor_sync(0xffffffffu, ax, o);
        ay += __shfl_xor_sync(0xffffffffu, ay, o);
        az += __shfl_xor_sync(0xffffffffu, az, o);
        aw += __shfl_xor_sync(0xffffffffu, aw, o);
    }
    float4 self = __ldg(&e4[n]);
    float di = g_dinv[n];
    // out = dinv[n]*(Sum_src e4s[src] + e4s[n])
    ax = (ax + self.x) * di;
    ay = (ay + self.y) * di;
    az = (az + self.z) * di;
    aw = (aw + self.w) * di;
    int f = lane * 2;
    const float2* sW2 = (const float2*)sW;
    float2 w0 = sW2[0 * 32 + lane], w1 = sW2[1 * 32 + lane];
    float2 w2 = sW2[2 * 32 + lane], w3 = sW2[3 * 32 + lane];
    float vx = fmaf(ax, w0.x, fmaf(ay, w1.x, fmaf(az, w2.x, fmaf(aw, w3.x, __ldg(&b1[f])))));
    float vy = fmaf(ax, w0.y, fmaf(ay, w1.y, fmaf(az, w2.y, fmaf(aw, w3.y, __ldg(&b1[f + 1])))));
    vx = fmaxf(vx, 0.f);
    vy = fmaxf(vy, 0.f);
    // warp LayerNorm
    float s = vx + vy;
#pragma unroll
    for (int o = 16; o; o >>= 1) s += __shfl_xor_sync(0xffffffffu, s, o);
    float mu = s * (1.f / 64.f);
    float dx = vx - mu, dy = vy - mu;
    float q = dx * dx + dy * dy;
#pragma unroll
    for (int o = 16; o; o >>= 1) q += __shfl_xor_sync(0xffffffffu, q, o);
    float rs = rsqrtf(q * (1.f / 64.f) + 1e-5f);
    float ox = fmaf(dx * rs, __ldg(&lng[f]), __ldg(&lnb[f]));
    float oy = fmaf(dy * rs, __ldg(&lng[f + 1]), __ldg(&lnb[f + 1]));
    ((float2*)g_bufA)[(size_t)n * 32 + lane] = make_float2(ox, oy);
}

// ---------------- layers 2/3 dense: hs = (bufA @ W) * dinv -> fp16 ----------------
__global__ __launch_bounds__(128) void k_mm(const float* __restrict__ W) {
    __shared__ float sW[HID * HID];
    int t = threadIdx.x;
    for (int i = t; i < HID * HID; i += 128) sW[i] = W[i];
    __syncthreads();
    int n = blockIdx.x * 128 + t;
    if (n >= NN) return;
    float acc[HID];
#pragma unroll
    for (int j = 0; j < HID; j++) acc[j] = 0.f;
    const float4* x4 = (const float4*)(g_bufA + (size_t)n * HID);
    for (int k4 = 0; k4 < 16; k4++) {
        float4 xv = x4[k4];
        const float4* w0 = (const float4*)(sW + (4 * k4 + 0) * HID);
        const float4* w1 = (const float4*)(sW + (4 * k4 + 1) * HID);
        const float4* w2 = (const float4*)(sW + (4 * k4 + 2) * HID);
        const float4* w3 = (const float4*)(sW + (4 * k4 + 3) * HID);
#pragma unroll
        for (int j = 0; j < 16; j++) {
            float4 a = w0[j], b = w1[j], c = w2[j], d = w3[j];
            acc[4 * j + 0] = fmaf(xv.x, a.x, fmaf(xv.y, b.x, fmaf(xv.z, c.x, fmaf(xv.w, d.x, acc[4 * j + 0]))));
            acc[4 * j + 1] = fmaf(xv.x, a.y, fmaf(xv.y, b.y, fmaf(xv.z, c.y, fmaf(xv.w, d.y, acc[4 * j + 1]))));
            acc[4 * j + 2] = fmaf(xv.x, a.z, fmaf(xv.y, b.z, fmaf(xv.z, c.z, fmaf(xv.w, d.z, acc[4 * j + 2]))));
            acc[4 * j + 3] = fmaf(xv.x, a.w, fmaf(xv.y, b.w, fmaf(xv.z, c.w, fmaf(xv.w, d.w, acc[4 * j + 3]))));
        }
    }
    float di = g_dinv[n];
    __half2* o = g_bufH + (size_t)n * 32;
#pragma unroll
    for (int j = 0; j < 32; j++)
        o[j] = __floats2half2_rn(acc[2 * j] * di, acc[2 * j + 1] * di);
}

// ---------------- fused 64-dim gather + relu (+LN | +pool), warp per node ----------------
template <bool LN, bool POOL>
__global__ __launch_bounds__(256) void k_gather(const float* __restrict__ bias,
                                                const float* __restrict__ lng,
                                                const float* __restrict__ lnb,
                                                const int* __restrict__ batch) {
    int n = (blockIdx.x * blockDim.x + threadIdx.x) >> 5;
    int lane = threadIdx.x & 31;
    if (n >= NN) return;
    const __half2* hs2 = g_bufH;
    float2 sf = __half22float2(__ldg(&hs2[(size_t)n * 32 + lane]));  // self term
    float accx = sf.x, accy = sf.y;
    int beg = g_rowbeg[n];
    int end = beg + g_z.deg[n];
    int e = beg;
    int m8 = beg + ((end - beg) & ~7);
    for (; e < m8; e += 8) {
        int s0 = __ldg(&g_col[e + 0]), s1 = __ldg(&g_col[e + 1]);
        int s2 = __ldg(&g_col[e + 2]), s3 = __ldg(&g_col[e + 3]);
        int s4 = __ldg(&g_col[e + 4]), s5 = __ldg(&g_col[e + 5]);
        int s6 = __ldg(&g_col[e + 6]), s7 = __ldg(&g_col[e + 7]);
        float2 v0 = __half22float2(__ldg(&hs2[(size_t)s0 * 32 + lane]));
        float2 v1 = __half22float2(__ldg(&hs2[(size_t)s1 * 32 + lane]));
        float2 v2 = __half22float2(__ldg(&hs2[(size_t)s2 * 32 + lane]));
        float2 v3 = __half22float2(__ldg(&hs2[(size_t)s3 * 32 + lane]));
        float2 v4 = __half22float2(__ldg(&hs2[(size_t)s4 * 32 + lane]));
        float2 v5 = __half22float2(__ldg(&hs2[(size_t)s5 * 32 + lane]));
        float2 v6 = __half22float2(__ldg(&hs2[(size_t)s6 * 32 + lane]));
        float2 v7 = __half22float2(__ldg(&hs2[(size_t)s7 * 32 + lane]));
        accx += ((v0.x + v1.x) + (v2.x + v3.x)) + ((v4.x + v5.x) + (v6.x + v7.x));
        accy += ((v0.y + v1.y) + (v2.y + v3.y)) + ((v4.y + v5.y) + (v6.y + v7.y));
    }
    for (; e < end; e++) {
        int s = __ldg(&g_col[e]);
        float2 v = __half22float2(__ldg(&hs2[(size_t)s * 32 + lane]));
        accx += v.x;
        accy += v.y;
    }
    float di = g_dinv[n];
    int f = lane * 2;
    float vx = fmaxf(fmaf(di, accx, __ldg(&bias[f])), 0.f);
    float vy = fmaxf(fmaf(di, accy, __ldg(&bias[f + 1])), 0.f);
    if (LN) {
        float s = vx + vy;
#pragma unroll
        for (int o = 16; o; o >>= 1) s += __shfl_xor_sync(0xffffffffu, s, o);
        float mu = s * (1.f / 64.f);
        float dx = vx - mu, dy = vy - mu;
        float q = dx * dx + dy * dy;
#pragma unroll
        for (int o = 16; o; o >>= 1) q += __shfl_xor_sync(0xffffffffu, q, o);
        float r = rsqrtf(q * (1.f / 64.f) + 1e-5f);
        vx = fmaf(dx * r, __ldg(&lng[f]), __ldg(&lnb[f]));
        vy = fmaf(dy * r, __ldg(&lng[f + 1]), __ldg(&lnb[f + 1]));
    }
    if (POOL) {
        int g = __ldg(&batch[n]);
        atomicAdd(&g_z.pool[g * HID + f], vx);
        atomicAdd(&g_z.pool[g * HID + f + 1], vy);
        if (lane == 0) atomicAdd(&g_z.cnt[g], 1);
    } else {
        ((float2*)g_bufA)[(size_t)n * 32 + lane] = make_float2(vx, vy);
    }
}

// ---------------- final MLP: out = (pool/cnt) @ pW1 + pb1, then @ pW2 + pb2 ----------------
__global__ __launch_bounds__(1024) void k_mlp(const float* __restrict__ pW1,
                                              const float* __restrict__ pb1,
                                              const float* __restrict__ pW2,
                                              const float* __restrict__ pb2,
                                              float* __restrict__ out) {
    __shared__ float sp[NG * HID];
    __shared__ float sh[NG * HID];
    int t = threadIdx.x;  // 1024
    for (int i = t; i < NG * HID; i += 1024) {
        int g = i >> 6;
        float c = (float)max(g_z.cnt[g], 1);
        sp[i] = g_z.pool[i] / c;
    }
    __syncthreads();
    for (int i = t; i < NG * HID; i += 1024) {
        int g = i >> 6, j = i & 63;
        float a = pb1[j];
        for (int k = 0; k < HID; k++) a = fmaf(sp[g * HID + k], pW1[k * HID + j], a);
        sh[i] = a;
    }
    __syncthreads();
    for (int i = t; i < NG * HID; i += 1024) {
        int g = i >> 6, j = i & 63;
        float a = pb2[j];
        for (int k = 0; k < HID; k++) a = fmaf(sh[g * HID + k], pW2[k * HID + j], a);
        out[i] = a;
    }
}

// ---------------- launcher ----------------
extern "C" void kernel_launch(void* const* d_in, const int* in_sizes, int n_in,
                              void* d_out, int out_size) {
    const int* node = (const int*)d_in[0];
    const int* src = (const int*)d_in[1];
    const int* dst = (const int*)d_in[2];
    const int* batch = (const int*)d_in[3];
    const float* emb = (const float*)d_in[4];
    const float* W1 = (const float*)d_in[5];
    const float* b1 = (const float*)d_in[6];
    const float* W2 = (const float*)d_in[7];
    const float* b2 = (const float*)d_in[8];
    const float* W3 = (const float*)d_in[9];
    const float* b3 = (const float*)d_in[10];
    const float* ln1g = (const float*)d_in[11];
    const float* ln1b = (const float*)d_in[12];
    const float* ln2g = (const float*)d_in[13];
    const float* ln2b = (const float*)d_in[14];
    const float* pW1 = (const float*)d_in[15];
    const float* pb1 = (const float*)d_in[16];
    const float* pW2 = (const float*)d_in[17];
    const float* pb2 = (const float*)d_in[18];
    float* out = (float*)d_out;

    // zero deg/cnt/ticket/pool in one shot
    void* zptr = nullptr;
    cudaGetSymbolAddress(&zptr, g_z);
    cudaMemsetAsync(zptr, 0, sizeof(ZBlock));

    const int TB = 256;
    k_deg<<<(NE + TB - 1) / TB, TB>>>(dst);
    k_scan<<<(NN + TB - 1) / TB, TB>>>(node, emb);
    k_fill<<<(NE + TB - 1) / TB, TB>>>(src, dst);

    dim3 gmm((NN + 127) / 128);
    dim3 ggt((NN * 32 + TB - 1) / TB);

    // layer 1 (fully fused, warp per node)
    k_layer1<<<ggt, TB>>>(W1, b1, ln1g, ln1b);
    // layer 2
    k_mm<<<gmm, 128>>>(W2);
    k_gather<true, false><<<ggt, TB>>>(b2, ln2g, ln2b, nullptr);
    // layer 3 (+ fused mean-pool accumulate)
    k_mm<<<gmm, 128>>>(W3);
    k_gather<false, true><<<ggt, TB>>>(b3, nullptr, nullptr, batch);
    // MLP head
    k_mlp<<<1, 1024>>>(pW1, pb1, pW2, pb2, out);
}